// round 4
// baseline (speedup 1.0000x reference)
#include <cuda_runtime.h>
#include <cuda_bf16.h>
#include <math.h>
#include <stdint.h>
#include <stddef.h>

// ---------------- problem constants ----------------
#define BWIN   4096
#define NTOK   49
#define DIMC   256
#define NH     8
#define HD     32
#define TDIM   768
#define MROWS  (BWIN * NTOK)   // 200704

// ---------------- scratch ----------------
__device__ float g_qkv[(size_t)MROWS * TDIM];
__device__ float g_attnout[(size_t)MROWS * DIMC];
__device__ float g_table[169 * NH];
__device__ float g_bias768[TDIM];
__device__ float g_cbias[64 * NH * 49 * 52];   // combined rpb+mask, row stride 52

// ---------------- tiny setup kernels ----------------
__global__ void fill_bias_kernel(const float* __restrict__ q_bias,
                                 const float* __restrict__ v_bias) {
    int t = threadIdx.x;
    if (t < 256)       g_bias768[t] = q_bias[t];
    else if (t < 512)  g_bias768[t] = 0.f;
    else               g_bias768[t] = v_bias[t - 512];
}

__global__ void cpb_table_kernel(const float* __restrict__ coords,
                                 const float* __restrict__ w1,
                                 const float* __restrict__ b1,
                                 const float* __restrict__ w2) {
    __shared__ float hid[512];
    __shared__ float part[64];
    int r = blockIdx.x;
    int tid = threadIdx.x;
    float c0 = coords[r * 2 + 0];
    float c1 = coords[r * 2 + 1];
    for (int j = tid; j < 512; j += 64) {
        float v = c0 * w1[j * 2 + 0] + c1 * w1[j * 2 + 1] + b1[j];
        hid[j] = v > 0.f ? v : 0.f;
    }
    __syncthreads();
    int head = tid & 7;
    int chunk = tid >> 3;
    float p = 0.f;
    const float* wrow = w2 + head * 512 + chunk * 64;
    const float* hrow = hid + chunk * 64;
#pragma unroll 8
    for (int j = 0; j < 64; ++j) p += hrow[j] * wrow[j];
    part[tid] = p;
    __syncthreads();
    if (tid < 8) {
        float s = 0.f;
#pragma unroll
        for (int c = 0; c < 8; ++c) s += part[c * 8 + tid];
        g_table[r * 8 + tid] = s;
    }
}

// combined bias: cbias[wm*8+h][i*52+j] = 16*sigmoid(table[rpi[i][j]][h]) + mask[wm][i][j]
__global__ void cbias_kernel(const int* __restrict__ rpi,
                             const float* __restrict__ mask) {
    int wm = blockIdx.x >> 3, h = blockIdx.x & 7;
    float* dst = g_cbias + (size_t)blockIdx.x * (49 * 52);
    const float* m = mask + wm * (NTOK * NTOK);
    for (int idx = threadIdx.x; idx < 49 * 52; idx += 256) {
        int i = idx / 52, j = idx % 52;
        float v = 0.f;
        if (j < 49) {
            float t = g_table[rpi[i * NTOK + j] * NH + h];
            v = 16.f / (1.f + expf(-t)) + m[i * NTOK + j];
        }
        dst[idx] = v;
    }
}

// ================= bf16x3 GEMM on legacy mma.sync (sm_80 path) =================
// C[M,N] = A[M,K] @ W[N,K]^T + bias[N]; M%128==0, N%128==0, K%32==0.
// 128x128 CTA tile, 8 warps (2M x 4N), warp tile 64x32, BK=32 (bf16 elems).
// ldmatrix-fed m16n8k16 bf16 MMA, 3-term split Ah*Wh + Ah*Wl + Al*Wh,
// fp32 register accumulators, double-buffered smem + register gmem prefetch.

#define ROWB   80                   // smem bytes per row (40 bf16, conflict-free LDSM)
#define MATB   (128 * ROWB)         // 10240 B per matrix half
#define STAGEB (4 * MATB)           // Ah | Al | Wh | Wl
#define GSMEM  (2 * STAGEB)         // 81920 B

__device__ __forceinline__ uint32_t s2u(const void* p) {
    uint32_t a;
    asm("{ .reg .u64 t; cvta.to.shared.u64 t, %1; cvt.u32.u64 %0, t; }"
        : "=r"(a) : "l"(p));
    return a;
}
__device__ __forceinline__ uint32_t pk(__nv_bfloat16 a, __nv_bfloat16 b) {
    return (uint32_t)__bfloat16_as_ushort(a) | ((uint32_t)__bfloat16_as_ushort(b) << 16);
}
__device__ __forceinline__ void split4(float4 v, uint2& hi, uint2& lo) {
    __nv_bfloat16 hx = __float2bfloat16(v.x), hy = __float2bfloat16(v.y);
    __nv_bfloat16 hz = __float2bfloat16(v.z), hw = __float2bfloat16(v.w);
    __nv_bfloat16 lx = __float2bfloat16(v.x - __bfloat162float(hx));
    __nv_bfloat16 ly = __float2bfloat16(v.y - __bfloat162float(hy));
    __nv_bfloat16 lz = __float2bfloat16(v.z - __bfloat162float(hz));
    __nv_bfloat16 lw = __float2bfloat16(v.w - __bfloat162float(hw));
    hi.x = pk(hx, hy); hi.y = pk(hz, hw);
    lo.x = pk(lx, ly); lo.y = pk(lz, lw);
}

#define LDSM4(r0, r1, r2, r3, a)                                              \
    asm volatile("ldmatrix.sync.aligned.m8n8.x4.shared.b16 {%0,%1,%2,%3}, [%4];" \
                 : "=r"(r0), "=r"(r1), "=r"(r2), "=r"(r3) : "r"(a))

#define MMA16816(c, a, b)                                                     \
    asm volatile(                                                             \
        "mma.sync.aligned.m16n8k16.row.col.f32.bf16.bf16.f32 "                \
        "{%0,%1,%2,%3},{%4,%5,%6,%7},{%8,%9},{%0,%1,%2,%3};"                  \
        : "+f"((c)[0]), "+f"((c)[1]), "+f"((c)[2]), "+f"((c)[3])              \
        : "r"((a)[0]), "r"((a)[1]), "r"((a)[2]), "r"((a)[3]),                 \
          "r"((b)[0]), "r"((b)[1]))

__global__ __launch_bounds__(256)
void gemm_bf16x3(const float* __restrict__ A, const float* __restrict__ W,
                 const float* __restrict__ bias, float* __restrict__ C,
                 int N, int K) {
    extern __shared__ char sm[];
    uint32_t smb = s2u(sm);

    int tid = threadIdx.x, lane = tid & 31, wid = tid >> 5;
    int warpM = wid & 1;       // 2 warps in M (64 rows each)
    int warpN = wid >> 1;      // 4 warps in N (32 cols each)
    size_t rowBlk = (size_t)blockIdx.y * 128;
    int colBlk = blockIdx.x * 128;

    float acc[4][4][4];
#pragma unroll
    for (int mt = 0; mt < 4; ++mt)
#pragma unroll
        for (int nt = 0; nt < 4; ++nt)
#pragma unroll
            for (int u = 0; u < 4; ++u) acc[mt][nt][u] = 0.f;

    // per-thread gmem->smem slots: 4 float4 per matrix (A tile 128x32 floats)
    int sr[4], sc[4];
#pragma unroll
    for (int ld = 0; ld < 4; ++ld) {
        int slot = tid + ld * 256;   // 0..1023
        sr[ld] = slot >> 3;          // 0..127
        sc[ld] = (slot & 7) << 2;    // 0,4,...,28 (floats)
    }

    // lane bases for ldmatrix (byte offsets within a matrix half)
    int g = lane >> 3, l7 = lane & 7;
    // A: matrices (g&1)->row+8, (g>>1)->k+8
    uint32_t aOff = (uint32_t)(warpM * 64 + (g & 1) * 8 + l7) * ROWB + (uint32_t)(g >> 1) * 16;
    // W: matrices (g>>1)->n+8, (g&1)->k+8
    uint32_t wOff = (uint32_t)(warpN * 32 + (g >> 1) * 8 + l7) * ROWB + (uint32_t)(g & 1) * 16;

    const int NCH = K >> 5;     // chunks of 32
    float4 pa[4], pw[4];

    // prefetch + store chunk 0
#pragma unroll
    for (int ld = 0; ld < 4; ++ld) {
        pa[ld] = *(const float4*)(A + (rowBlk + sr[ld]) * (size_t)K + sc[ld]);
        pw[ld] = *(const float4*)(W + (size_t)(colBlk + sr[ld]) * K + sc[ld]);
    }
    {
        char* st = sm;
#pragma unroll
        for (int ld = 0; ld < 4; ++ld) {
            uint32_t off = (uint32_t)sr[ld] * ROWB + (uint32_t)sc[ld] * 2;
            uint2 h, l;
            split4(pa[ld], h, l);
            *(uint2*)(st + off) = h;
            *(uint2*)(st + MATB + off) = l;
            split4(pw[ld], h, l);
            *(uint2*)(st + 2 * MATB + off) = h;
            *(uint2*)(st + 3 * MATB + off) = l;
        }
    }
    __syncthreads();

    for (int ch = 0; ch < NCH; ++ch) {
        if (ch + 1 < NCH) {
            int koff = (ch + 1) << 5;
#pragma unroll
            for (int ld = 0; ld < 4; ++ld) {
                pa[ld] = *(const float4*)(A + (rowBlk + sr[ld]) * (size_t)K + koff + sc[ld]);
                pw[ld] = *(const float4*)(W + (size_t)(colBlk + sr[ld]) * K + koff + sc[ld]);
            }
        }

        uint32_t stage = smb + (uint32_t)(ch & 1) * STAGEB;
#pragma unroll
        for (int ks = 0; ks < 2; ++ks) {
            uint32_t kb = (uint32_t)ks * 32;   // 16 bf16 = 32 bytes
            uint32_t ah[4][4], al[4][4], wh[4][2], wl[4][2];
#pragma unroll
            for (int mt = 0; mt < 4; ++mt) {
                uint32_t ad = stage + aOff + (uint32_t)mt * (16 * ROWB) + kb;
                LDSM4(ah[mt][0], ah[mt][1], ah[mt][2], ah[mt][3], ad);
                LDSM4(al[mt][0], al[mt][1], al[mt][2], al[mt][3], ad + MATB);
            }
#pragma unroll
            for (int p = 0; p < 2; ++p) {
                uint32_t wd = stage + 2 * MATB + wOff + (uint32_t)p * (16 * ROWB) + kb;
                uint32_t t0, t1, t2, t3;
                LDSM4(t0, t1, t2, t3, wd);
                wh[2 * p][0] = t0; wh[2 * p][1] = t1;
                wh[2 * p + 1][0] = t2; wh[2 * p + 1][1] = t3;
                LDSM4(t0, t1, t2, t3, wd + MATB);
                wl[2 * p][0] = t0; wl[2 * p][1] = t1;
                wl[2 * p + 1][0] = t2; wl[2 * p + 1][1] = t3;
            }
#pragma unroll
            for (int mt = 0; mt < 4; ++mt)
#pragma unroll
                for (int nt = 0; nt < 4; ++nt) {
                    MMA16816(acc[mt][nt], ah[mt], wh[nt]);
                    MMA16816(acc[mt][nt], ah[mt], wl[nt]);
                    MMA16816(acc[mt][nt], al[mt], wh[nt]);
                }
        }

        if (ch + 1 < NCH) {
            char* st = sm + ((ch + 1) & 1) * STAGEB;
#pragma unroll
            for (int ld = 0; ld < 4; ++ld) {
                uint32_t off = (uint32_t)sr[ld] * ROWB + (uint32_t)sc[ld] * 2;
                uint2 h, l;
                split4(pa[ld], h, l);
                *(uint2*)(st + off) = h;
                *(uint2*)(st + MATB + off) = l;
                split4(pw[ld], h, l);
                *(uint2*)(st + 2 * MATB + off) = h;
                *(uint2*)(st + 3 * MATB + off) = l;
            }
        }
        __syncthreads();
    }

    // epilogue: thread holds rows (lane>>2, +8), cols (lane&3)*2, +1
#pragma unroll
    for (int nt = 0; nt < 4; ++nt) {
        int col = colBlk + warpN * 32 + nt * 8 + (lane & 3) * 2;
        float2 bv = *(const float2*)(bias + col);
#pragma unroll
        for (int mt = 0; mt < 4; ++mt) {
            size_t row0 = rowBlk + warpM * 64 + mt * 16 + (lane >> 2);
            float2 o0, o1;
            o0.x = acc[mt][nt][0] + bv.x; o0.y = acc[mt][nt][1] + bv.y;
            o1.x = acc[mt][nt][2] + bv.x; o1.y = acc[mt][nt][3] + bv.y;
            *(float2*)(C + row0 * (size_t)N + col)       = o0;
            *(float2*)(C + (row0 + 8) * (size_t)N + col) = o1;
        }
    }
}

// ================= attention: one block per (window, head) =================
__global__ __launch_bounds__(256)
void attn_kernel(const float* __restrict__ logit_scale) {
    __shared__ float sq[52][36];
    __shared__ float sk[52][36];
    __shared__ float sv[52][36];
    __shared__ float sattn[52][53];

    int blk = blockIdx.x;
    int b = blk >> 3;
    int h = blk & 7;
    int tid = threadIdx.x;
    int wid = tid >> 5, lane = tid & 31;

    for (int idx = tid; idx < NTOK * 8; idx += 256) {
        int n = idx >> 3, d4 = (idx & 7) << 2;
        size_t base = ((size_t)b * NTOK + n) * TDIM + h * HD + d4;
        *(float4*)&sq[n][d4] = *(const float4*)(g_qkv + base);
        *(float4*)&sk[n][d4] = *(const float4*)(g_qkv + base + 256);
        *(float4*)&sv[n][d4] = *(const float4*)(g_qkv + base + 512);
    }
    if (tid < 108) {
        int r = 49 + tid / 36, c = tid % 36;
        sq[r][c] = 0.f; sk[r][c] = 0.f; sv[r][c] = 0.f;
    }
    if (tid < 159) {
        sattn[49 + tid / 53][tid % 53] = 0.f;
    }
    __syncthreads();

    float sc = expf(fminf(logit_scale[h], 4.60517019f));

    for (int r = wid; r < NTOK; r += 8) {
        float qv = sq[r][lane];
        float s = qv * qv;
#pragma unroll
        for (int o = 16; o; o >>= 1) s += __shfl_xor_sync(0xffffffffu, s, o);
        sq[r][lane] = qv * rsqrtf(s + 1e-6f) * sc;
        float kv = sk[r][lane];
        float s2 = kv * kv;
#pragma unroll
        for (int o = 16; o; o >>= 1) s2 += __shfl_xor_sync(0xffffffffu, s2, o);
        sk[r][lane] = kv * rsqrtf(s2 + 1e-6f);
    }
    __syncthreads();

    // QK^T: 13x13 tiles of 4x4
    if (tid < 169) {
        int ti = tid / 13, tj = tid % 13;
        int i0 = 4 * ti, j0 = 4 * tj;
        float a4[4][4];
#pragma unroll
        for (int u = 0; u < 4; ++u)
#pragma unroll
            for (int w = 0; w < 4; ++w) a4[u][w] = 0.f;
#pragma unroll
        for (int d = 0; d < HD; d += 4) {
            float4 qv[4], kv[4];
#pragma unroll
            for (int u = 0; u < 4; ++u) qv[u] = *(const float4*)&sq[i0 + u][d];
#pragma unroll
            for (int w = 0; w < 4; ++w) kv[w] = *(const float4*)&sk[j0 + w][d];
#pragma unroll
            for (int u = 0; u < 4; ++u)
#pragma unroll
                for (int w = 0; w < 4; ++w) {
                    a4[u][w] = fmaf(qv[u].x, kv[w].x, a4[u][w]);
                    a4[u][w] = fmaf(qv[u].y, kv[w].y, a4[u][w]);
                    a4[u][w] = fmaf(qv[u].z, kv[w].z, a4[u][w]);
                    a4[u][w] = fmaf(qv[u].w, kv[w].w, a4[u][w]);
                }
        }
        const float* cb = g_cbias + ((size_t)((b & 63) * NH + h)) * (49 * 52);
#pragma unroll
        for (int u = 0; u < 4; ++u) {
            int i = i0 + u;
            if (i < NTOK) {
#pragma unroll
                for (int w = 0; w < 4; ++w) {
                    int j = j0 + w;
                    if (j < NTOK)
                        sattn[i][j] = a4[u][w] + __ldg(cb + i * 52 + j);
                }
            }
        }
    }
    __syncthreads();

    for (int r = wid; r < NTOK; r += 8) {
        float v0 = sattn[r][lane];
        float v1 = (lane + 32 < NTOK) ? sattn[r][lane + 32] : -1e30f;
        float mx = fmaxf(v0, v1);
#pragma unroll
        for (int o = 16; o; o >>= 1) mx = fmaxf(mx, __shfl_xor_sync(0xffffffffu, mx, o));
        float e0 = expf(v0 - mx);
        float e1 = (lane + 32 < NTOK) ? expf(v1 - mx) : 0.f;
        float sm = e0 + e1;
#pragma unroll
        for (int o = 16; o; o >>= 1) sm += __shfl_xor_sync(0xffffffffu, sm, o);
        float inv = 1.f / sm;
        sattn[r][lane] = e0 * inv;
        if (lane + 32 < NTOK) sattn[r][lane + 32] = e1 * inv;
    }
    __syncthreads();

    // out = attn @ v : 13 i-tiles x 8 d-tiles of 4x4
    if (tid < 104) {
        int ti = tid >> 3, dt = tid & 7;
        int i0 = 4 * ti, d0 = 4 * dt;
        float a4[4][4];
#pragma unroll
        for (int u = 0; u < 4; ++u)
#pragma unroll
            for (int w = 0; w < 4; ++w) a4[u][w] = 0.f;
        for (int j = 0; j < NTOK; ++j) {
            float4 vv = *(const float4*)&sv[j][d0];
            float a0 = sattn[i0 + 0][j], a1 = sattn[i0 + 1][j];
            float a2 = sattn[i0 + 2][j], a3 = sattn[i0 + 3][j];
            a4[0][0] = fmaf(a0, vv.x, a4[0][0]); a4[0][1] = fmaf(a0, vv.y, a4[0][1]);
            a4[0][2] = fmaf(a0, vv.z, a4[0][2]); a4[0][3] = fmaf(a0, vv.w, a4[0][3]);
            a4[1][0] = fmaf(a1, vv.x, a4[1][0]); a4[1][1] = fmaf(a1, vv.y, a4[1][1]);
            a4[1][2] = fmaf(a1, vv.z, a4[1][2]); a4[1][3] = fmaf(a1, vv.w, a4[1][3]);
            a4[2][0] = fmaf(a2, vv.x, a4[2][0]); a4[2][1] = fmaf(a2, vv.y, a4[2][1]);
            a4[2][2] = fmaf(a2, vv.z, a4[2][2]); a4[2][3] = fmaf(a2, vv.w, a4[2][3]);
            a4[3][0] = fmaf(a3, vv.x, a4[3][0]); a4[3][1] = fmaf(a3, vv.y, a4[3][1]);
            a4[3][2] = fmaf(a3, vv.z, a4[3][2]); a4[3][3] = fmaf(a3, vv.w, a4[3][3]);
        }
#pragma unroll
        for (int u = 0; u < 4; ++u) {
            int i = i0 + u;
            if (i < NTOK) {
                float4 o = make_float4(a4[u][0], a4[u][1], a4[u][2], a4[u][3]);
                *(float4*)(g_attnout + ((size_t)b * NTOK + i) * DIMC + h * HD + d0) = o;
            }
        }
    }
}

// ---------------- launch ----------------
extern "C" void kernel_launch(void* const* d_in, const int* in_sizes, int n_in,
                              void* d_out, int out_size) {
    const float* x           = (const float*)d_in[0];
    const float* qkv_w       = (const float*)d_in[1];
    const float* q_bias      = (const float*)d_in[2];
    const float* v_bias      = (const float*)d_in[3];
    const float* logit_scale = (const float*)d_in[4];
    const float* cpb_w1      = (const float*)d_in[5];
    const float* cpb_b1      = (const float*)d_in[6];
    const float* cpb_w2      = (const float*)d_in[7];
    const float* coords      = (const float*)d_in[8];
    const int*   rpi         = (const int*)  d_in[9];
    const float* mask        = (const float*)d_in[10];
    const float* proj_w      = (const float*)d_in[11];
    const float* proj_b      = (const float*)d_in[12];
    float* out = (float*)d_out;

    float *qkv_ptr = nullptr, *ao_ptr = nullptr, *b768_ptr = nullptr;
    cudaGetSymbolAddress((void**)&qkv_ptr, g_qkv);
    cudaGetSymbolAddress((void**)&ao_ptr, g_attnout);
    cudaGetSymbolAddress((void**)&b768_ptr, g_bias768);

    cudaFuncSetAttribute(gemm_bf16x3,
                         cudaFuncAttributeMaxDynamicSharedMemorySize, GSMEM);

    fill_bias_kernel<<<1, 768>>>(q_bias, v_bias);
    cpb_table_kernel<<<169, 64>>>(coords, cpb_w1, cpb_b1, cpb_w2);
    cbias_kernel<<<64 * NH, 256>>>(rpi, mask);

    // qkv = x @ qkv_w^T + [q_bias, 0, v_bias]
    gemm_bf16x3<<<dim3(TDIM / 128, MROWS / 128), 256, GSMEM>>>(
        x, qkv_w, b768_ptr, qkv_ptr, TDIM, DIMC);

    attn_kernel<<<BWIN * NH, 256>>>(logit_scale);

    // out = attn_out @ proj_w^T + proj_b
    gemm_bf16x3<<<dim3(DIMC / 128, MROWS / 128), 256, GSMEM>>>(
        ao_ptr, proj_w, proj_b, out, DIMC, DIMC);
}

// round 5
// speedup vs baseline: 1.1714x; 1.1714x over previous
#include <cuda_runtime.h>
#include <cuda_bf16.h>
#include <math.h>
#include <stdint.h>
#include <stddef.h>

// ---------------- problem constants ----------------
#define BWIN   4096
#define NTOK   49
#define DIMC   256
#define NH     8
#define HD     32
#define TDIM   768
#define MROWS  (BWIN * NTOK)   // 200704

// ---------------- scratch ----------------
__device__ float g_qkv[(size_t)MROWS * TDIM];
__device__ __nv_bfloat16 g_xhi[(size_t)MROWS * DIMC];
__device__ __nv_bfloat16 g_xlo[(size_t)MROWS * DIMC];
__device__ __nv_bfloat16 g_aohi[(size_t)MROWS * DIMC];
__device__ __nv_bfloat16 g_aolo[(size_t)MROWS * DIMC];
__device__ __nv_bfloat16 g_wqhi[TDIM * DIMC];
__device__ __nv_bfloat16 g_wqlo[TDIM * DIMC];
__device__ __nv_bfloat16 g_wphi[DIMC * DIMC];
__device__ __nv_bfloat16 g_wplo[DIMC * DIMC];
__device__ float g_table[169 * NH];
__device__ float g_bias768[TDIM];
__device__ float g_cbias[64 * NH * 49 * 52];

__device__ __forceinline__ uint32_t pk(__nv_bfloat16 a, __nv_bfloat16 b) {
    return (uint32_t)__bfloat16_as_ushort(a) | ((uint32_t)__bfloat16_as_ushort(b) << 16);
}

// ---------------- split fp32 -> bf16 hi/lo ----------------
__global__ void split_kernel(const float* __restrict__ src,
                             __nv_bfloat16* __restrict__ hi,
                             __nv_bfloat16* __restrict__ lo, int n4) {
    int i = blockIdx.x * 256 + threadIdx.x;
    if (i >= n4) return;
    float4 v = ((const float4*)src)[i];
    __nv_bfloat16 hx = __float2bfloat16(v.x), hy = __float2bfloat16(v.y);
    __nv_bfloat16 hz = __float2bfloat16(v.z), hw = __float2bfloat16(v.w);
    uint2 H = make_uint2(pk(hx, hy), pk(hz, hw));
    uint2 L = make_uint2(
        pk(__float2bfloat16(v.x - __bfloat162float(hx)),
           __float2bfloat16(v.y - __bfloat162float(hy))),
        pk(__float2bfloat16(v.z - __bfloat162float(hz)),
           __float2bfloat16(v.w - __bfloat162float(hw))));
    ((uint2*)hi)[i] = H;
    ((uint2*)lo)[i] = L;
}

// ---------------- tiny setup kernels ----------------
__global__ void fill_bias_kernel(const float* __restrict__ q_bias,
                                 const float* __restrict__ v_bias) {
    int t = threadIdx.x;
    if (t < 256)       g_bias768[t] = q_bias[t];
    else if (t < 512)  g_bias768[t] = 0.f;
    else               g_bias768[t] = v_bias[t - 512];
}

__global__ void cpb_table_kernel(const float* __restrict__ coords,
                                 const float* __restrict__ w1,
                                 const float* __restrict__ b1,
                                 const float* __restrict__ w2) {
    __shared__ float hid[512];
    __shared__ float part[64];
    int r = blockIdx.x;
    int tid = threadIdx.x;
    float c0 = coords[r * 2 + 0];
    float c1 = coords[r * 2 + 1];
    for (int j = tid; j < 512; j += 64) {
        float v = c0 * w1[j * 2 + 0] + c1 * w1[j * 2 + 1] + b1[j];
        hid[j] = v > 0.f ? v : 0.f;
    }
    __syncthreads();
    int head = tid & 7;
    int chunk = tid >> 3;
    float p = 0.f;
    const float* wrow = w2 + head * 512 + chunk * 64;
    const float* hrow = hid + chunk * 64;
#pragma unroll 8
    for (int j = 0; j < 64; ++j) p += hrow[j] * wrow[j];
    part[tid] = p;
    __syncthreads();
    if (tid < 8) {
        float s = 0.f;
#pragma unroll
        for (int c = 0; c < 8; ++c) s += part[c * 8 + tid];
        g_table[r * 8 + tid] = s;
    }
}

__global__ void cbias_kernel(const int* __restrict__ rpi,
                             const float* __restrict__ mask) {
    int wm = blockIdx.x >> 3, h = blockIdx.x & 7;
    float* dst = g_cbias + (size_t)blockIdx.x * (49 * 52);
    const float* m = mask + wm * (NTOK * NTOK);
    for (int idx = threadIdx.x; idx < 49 * 52; idx += 256) {
        int i = idx / 52, j = idx % 52;
        float v = 0.f;
        if (j < 49) {
            float t = g_table[rpi[i * NTOK + j] * NH + h];
            v = 16.f / (1.f + expf(-t)) + m[i * NTOK + j];
        }
        dst[idx] = v;
    }
}

// ================= bf16x3 GEMM, cp.async 4-stage pipeline =================
// C[M,N] = A[M,K] @ W[N,K]^T + bias[N]; A,W pre-split bf16 hi/lo.
// 128x128 CTA tile, 8 warps (2M x 4N), warp tile 64x32, KC=32 bf16.

#define KC     32
#define ROWB   80
#define MATB   (128 * ROWB)      // 10240
#define STAGEB (4 * MATB)        // 40960: Ah | Al | Wh | Wl
#define NSTG   4
#define GSMEM  (NSTG * STAGEB)   // 163840

__device__ __forceinline__ uint32_t s2u(const void* p) {
    uint32_t a;
    asm("{ .reg .u64 t; cvta.to.shared.u64 t, %1; cvt.u32.u64 %0, t; }"
        : "=r"(a) : "l"(p));
    return a;
}

#define CPA16(saddr, gaddr)                                                   \
    asm volatile("cp.async.cg.shared.global [%0], [%1], 16;"                  \
                 :: "r"(saddr), "l"(gaddr))
#define CPA_COMMIT() asm volatile("cp.async.commit_group;" ::: "memory")
#define CPA_WAIT2()  asm volatile("cp.async.wait_group 2;" ::: "memory")

#define LDSM4(r0, r1, r2, r3, a)                                              \
    asm volatile("ldmatrix.sync.aligned.m8n8.x4.shared.b16 {%0,%1,%2,%3}, [%4];" \
                 : "=r"(r0), "=r"(r1), "=r"(r2), "=r"(r3) : "r"(a))

#define MMA16816(c, a, b)                                                     \
    asm volatile(                                                             \
        "mma.sync.aligned.m16n8k16.row.col.f32.bf16.bf16.f32 "                \
        "{%0,%1,%2,%3},{%4,%5,%6,%7},{%8,%9},{%0,%1,%2,%3};"                  \
        : "+f"((c)[0]), "+f"((c)[1]), "+f"((c)[2]), "+f"((c)[3])              \
        : "r"((a)[0]), "r"((a)[1]), "r"((a)[2]), "r"((a)[3]),                 \
          "r"((b)[0]), "r"((b)[1]))

__global__ __launch_bounds__(256)
void gemm_bf16x3(const __nv_bfloat16* __restrict__ Ahi,
                 const __nv_bfloat16* __restrict__ Alo,
                 const __nv_bfloat16* __restrict__ Whi,
                 const __nv_bfloat16* __restrict__ Wlo,
                 const float* __restrict__ bias, float* __restrict__ C,
                 int N, int K) {
    extern __shared__ char sm[];
    uint32_t smb = s2u(sm);

    int tid = threadIdx.x, lane = tid & 31, wid = tid >> 5;
    int warpM = wid & 1;
    int warpN = wid >> 1;
    size_t rowBlk = (size_t)blockIdx.y * 128;
    int colBlk = blockIdx.x * 128;

    float acc[4][4][4];
#pragma unroll
    for (int mt = 0; mt < 4; ++mt)
#pragma unroll
        for (int nt = 0; nt < 4; ++nt)
#pragma unroll
            for (int u = 0; u < 4; ++u) acc[mt][nt][u] = 0.f;

    // load mapping: 2 slots/thread/matrix; slot -> (row, 16B col)
    int lr[2], lc[2];
#pragma unroll
    for (int i = 0; i < 2; ++i) {
        int slot = tid + i * 256;     // 0..511
        lr[i] = slot >> 2;            // 0..127
        lc[i] = slot & 3;             // 16B chunk (8 bf16)
    }
    const __nv_bfloat16* gA[2] = {Ahi, Alo};
    const __nv_bfloat16* gW[2] = {Whi, Wlo};

    const int NCH = K >> 5;           // 8 for K=256

    // ldmatrix lane bases (validated layout from R4, ROWB=80)
    int g = lane >> 3, l7 = lane & 7;
    uint32_t aOff = (uint32_t)(warpM * 64 + (g & 1) * 8 + l7) * ROWB + (uint32_t)(g >> 1) * 16;
    uint32_t wOff = (uint32_t)(warpN * 32 + (g >> 1) * 8 + l7) * ROWB + (uint32_t)(g & 1) * 16;

#define ISSUE_CHUNK(ch)                                                       \
    do {                                                                      \
        uint32_t stg_ = smb + (uint32_t)((ch) & 3) * STAGEB;                  \
        int koff_ = (ch) * KC;                                                \
        _Pragma("unroll")                                                     \
        for (int i_ = 0; i_ < 2; ++i_) {                                      \
            uint32_t so_ = stg_ + (uint32_t)lr[i_] * ROWB + (uint32_t)lc[i_] * 16; \
            size_t ge_ = (rowBlk + lr[i_]) * (size_t)K + koff_ + lc[i_] * 8;  \
            size_t gw_ = (size_t)(colBlk + lr[i_]) * K + koff_ + lc[i_] * 8;  \
            CPA16(so_,            gA[0] + ge_);                               \
            CPA16(so_ + MATB,     gA[1] + ge_);                               \
            CPA16(so_ + 2 * MATB, gW[0] + gw_);                               \
            CPA16(so_ + 3 * MATB, gW[1] + gw_);                               \
        }                                                                     \
    } while (0)

    // prologue: stages 0..2
    ISSUE_CHUNK(0); CPA_COMMIT();
    ISSUE_CHUNK(1); CPA_COMMIT();
    ISSUE_CHUNK(2); CPA_COMMIT();

    for (int ch = 0; ch < NCH; ++ch) {
        CPA_WAIT2();
        __syncthreads();
        if (ch + 3 < NCH) ISSUE_CHUNK(ch + 3);
        CPA_COMMIT();

        uint32_t stg = smb + (uint32_t)(ch & 3) * STAGEB;
#pragma unroll
        for (int ks = 0; ks < 2; ++ks) {
            uint32_t kb = (uint32_t)ks * 32;
            uint32_t ah[4][4], al[4][4], wh[4][2], wl[4][2];
#pragma unroll
            for (int mt = 0; mt < 4; ++mt) {
                uint32_t ad = stg + aOff + (uint32_t)mt * (16 * ROWB) + kb;
                LDSM4(ah[mt][0], ah[mt][1], ah[mt][2], ah[mt][3], ad);
                LDSM4(al[mt][0], al[mt][1], al[mt][2], al[mt][3], ad + MATB);
            }
#pragma unroll
            for (int p = 0; p < 2; ++p) {
                uint32_t wd = stg + 2 * MATB + wOff + (uint32_t)p * (16 * ROWB) + kb;
                uint32_t t0, t1, t2, t3;
                LDSM4(t0, t1, t2, t3, wd);
                wh[2 * p][0] = t0; wh[2 * p][1] = t1;
                wh[2 * p + 1][0] = t2; wh[2 * p + 1][1] = t3;
                LDSM4(t0, t1, t2, t3, wd + MATB);
                wl[2 * p][0] = t0; wl[2 * p][1] = t1;
                wl[2 * p + 1][0] = t2; wl[2 * p + 1][1] = t3;
            }
#pragma unroll
            for (int mt = 0; mt < 4; ++mt)
#pragma unroll
                for (int nt = 0; nt < 4; ++nt) {
                    MMA16816(acc[mt][nt], ah[mt], wh[nt]);
                    MMA16816(acc[mt][nt], ah[mt], wl[nt]);
                    MMA16816(acc[mt][nt], al[mt], wh[nt]);
                }
        }
    }

    // epilogue
#pragma unroll
    for (int nt = 0; nt < 4; ++nt) {
        int col = colBlk + warpN * 32 + nt * 8 + (lane & 3) * 2;
        float2 bv = *(const float2*)(bias + col);
#pragma unroll
        for (int mt = 0; mt < 4; ++mt) {
            size_t row0 = rowBlk + warpM * 64 + mt * 16 + (lane >> 2);
            float2 o0, o1;
            o0.x = acc[mt][nt][0] + bv.x; o0.y = acc[mt][nt][1] + bv.y;
            o1.x = acc[mt][nt][2] + bv.x; o1.y = acc[mt][nt][3] + bv.y;
            *(float2*)(C + row0 * (size_t)N + col)       = o0;
            *(float2*)(C + (row0 + 8) * (size_t)N + col) = o1;
        }
    }
}

// ================= attention: one block per (window, head) =================
__global__ __launch_bounds__(256)
void attn_kernel(const float* __restrict__ logit_scale) {
    __shared__ float sq[52][36];
    __shared__ float sk[52][36];
    __shared__ float sv[52][36];
    __shared__ float sattn[52][53];

    int blk = blockIdx.x;
    int b = blk >> 3;
    int h = blk & 7;
    int tid = threadIdx.x;
    int wid = tid >> 5, lane = tid & 31;

    for (int idx = tid; idx < NTOK * 8; idx += 256) {
        int n = idx >> 3, d4 = (idx & 7) << 2;
        size_t base = ((size_t)b * NTOK + n) * TDIM + h * HD + d4;
        *(float4*)&sq[n][d4] = *(const float4*)(g_qkv + base);
        *(float4*)&sk[n][d4] = *(const float4*)(g_qkv + base + 256);
        *(float4*)&sv[n][d4] = *(const float4*)(g_qkv + base + 512);
    }
    if (tid < 108) {
        int r = 49 + tid / 36, c = tid % 36;
        sq[r][c] = 0.f; sk[r][c] = 0.f; sv[r][c] = 0.f;
    }
    if (tid < 159) {
        sattn[49 + tid / 53][tid % 53] = 0.f;
    }
    __syncthreads();

    float sc = expf(fminf(logit_scale[h], 4.60517019f));

    for (int r = wid; r < NTOK; r += 8) {
        float qv = sq[r][lane];
        float s = qv * qv;
#pragma unroll
        for (int o = 16; o; o >>= 1) s += __shfl_xor_sync(0xffffffffu, s, o);
        sq[r][lane] = qv * rsqrtf(s + 1e-6f) * sc;
        float kv = sk[r][lane];
        float s2 = kv * kv;
#pragma unroll
        for (int o = 16; o; o >>= 1) s2 += __shfl_xor_sync(0xffffffffu, s2, o);
        sk[r][lane] = kv * rsqrtf(s2 + 1e-6f);
    }
    __syncthreads();

    // QK^T: 13x13 tiles of 4x4
    if (tid < 169) {
        int ti = tid / 13, tj = tid % 13;
        int i0 = 4 * ti, j0 = 4 * tj;
        float a4[4][4];
#pragma unroll
        for (int u = 0; u < 4; ++u)
#pragma unroll
            for (int w = 0; w < 4; ++w) a4[u][w] = 0.f;
#pragma unroll
        for (int d = 0; d < HD; d += 4) {
            float4 qv[4], kv[4];
#pragma unroll
            for (int u = 0; u < 4; ++u) qv[u] = *(const float4*)&sq[i0 + u][d];
#pragma unroll
            for (int w = 0; w < 4; ++w) kv[w] = *(const float4*)&sk[j0 + w][d];
#pragma unroll
            for (int u = 0; u < 4; ++u)
#pragma unroll
                for (int w = 0; w < 4; ++w) {
                    a4[u][w] = fmaf(qv[u].x, kv[w].x, a4[u][w]);
                    a4[u][w] = fmaf(qv[u].y, kv[w].y, a4[u][w]);
                    a4[u][w] = fmaf(qv[u].z, kv[w].z, a4[u][w]);
                    a4[u][w] = fmaf(qv[u].w, kv[w].w, a4[u][w]);
                }
        }
        const float* cb = g_cbias + ((size_t)((b & 63) * NH + h)) * (49 * 52);
#pragma unroll
        for (int u = 0; u < 4; ++u) {
            int i = i0 + u;
            if (i < NTOK) {
#pragma unroll
                for (int w = 0; w < 4; ++w) {
                    int j = j0 + w;
                    if (j < NTOK)
                        sattn[i][j] = a4[u][w] + __ldg(cb + i * 52 + j);
                }
            }
        }
    }
    __syncthreads();

    for (int r = wid; r < NTOK; r += 8) {
        float v0 = sattn[r][lane];
        float v1 = (lane + 32 < NTOK) ? sattn[r][lane + 32] : -1e30f;
        float mx = fmaxf(v0, v1);
#pragma unroll
        for (int o = 16; o; o >>= 1) mx = fmaxf(mx, __shfl_xor_sync(0xffffffffu, mx, o));
        float e0 = expf(v0 - mx);
        float e1 = (lane + 32 < NTOK) ? expf(v1 - mx) : 0.f;
        float sm = e0 + e1;
#pragma unroll
        for (int o = 16; o; o >>= 1) sm += __shfl_xor_sync(0xffffffffu, sm, o);
        float inv = 1.f / sm;
        sattn[r][lane] = e0 * inv;
        if (lane + 32 < NTOK) sattn[r][lane + 32] = e1 * inv;
    }
    __syncthreads();

    // out = attn @ v, write bf16 hi/lo directly
    if (tid < 104) {
        int ti = tid >> 3, dt = tid & 7;
        int i0 = 4 * ti, d0 = 4 * dt;
        float a4[4][4];
#pragma unroll
        for (int u = 0; u < 4; ++u)
#pragma unroll
            for (int w = 0; w < 4; ++w) a4[u][w] = 0.f;
        for (int j = 0; j < NTOK; ++j) {
            float4 vv = *(const float4*)&sv[j][d0];
            float a0 = sattn[i0 + 0][j], a1 = sattn[i0 + 1][j];
            float a2 = sattn[i0 + 2][j], a3 = sattn[i0 + 3][j];
            a4[0][0] = fmaf(a0, vv.x, a4[0][0]); a4[0][1] = fmaf(a0, vv.y, a4[0][1]);
            a4[0][2] = fmaf(a0, vv.z, a4[0][2]); a4[0][3] = fmaf(a0, vv.w, a4[0][3]);
            a4[1][0] = fmaf(a1, vv.x, a4[1][0]); a4[1][1] = fmaf(a1, vv.y, a4[1][1]);
            a4[1][2] = fmaf(a1, vv.z, a4[1][2]); a4[1][3] = fmaf(a1, vv.w, a4[1][3]);
            a4[2][0] = fmaf(a2, vv.x, a4[2][0]); a4[2][1] = fmaf(a2, vv.y, a4[2][1]);
            a4[2][2] = fmaf(a2, vv.z, a4[2][2]); a4[2][3] = fmaf(a2, vv.w, a4[2][3]);
            a4[3][0] = fmaf(a3, vv.x, a4[3][0]); a4[3][1] = fmaf(a3, vv.y, a4[3][1]);
            a4[3][2] = fmaf(a3, vv.z, a4[3][2]); a4[3][3] = fmaf(a3, vv.w, a4[3][3]);
        }
#pragma unroll
        for (int u = 0; u < 4; ++u) {
            int i = i0 + u;
            if (i < NTOK) {
                size_t idx = ((size_t)b * NTOK + i) * DIMC + h * HD + d0;
                __nv_bfloat16 h0 = __float2bfloat16(a4[u][0]);
                __nv_bfloat16 h1 = __float2bfloat16(a4[u][1]);
                __nv_bfloat16 h2 = __float2bfloat16(a4[u][2]);
                __nv_bfloat16 h3 = __float2bfloat16(a4[u][3]);
                uint2 H = make_uint2(pk(h0, h1), pk(h2, h3));
                uint2 L = make_uint2(
                    pk(__float2bfloat16(a4[u][0] - __bfloat162float(h0)),
                       __float2bfloat16(a4[u][1] - __bfloat162float(h1))),
                    pk(__float2bfloat16(a4[u][2] - __bfloat162float(h2)),
                       __float2bfloat16(a4[u][3] - __bfloat162float(h3))));
                *(uint2*)(g_aohi + idx) = H;
                *(uint2*)(g_aolo + idx) = L;
            }
        }
    }
}

// ---------------- launch ----------------
extern "C" void kernel_launch(void* const* d_in, const int* in_sizes, int n_in,
                              void* d_out, int out_size) {
    const float* x           = (const float*)d_in[0];
    const float* qkv_w       = (const float*)d_in[1];
    const float* q_bias      = (const float*)d_in[2];
    const float* v_bias      = (const float*)d_in[3];
    const float* logit_scale = (const float*)d_in[4];
    const float* cpb_w1      = (const float*)d_in[5];
    const float* cpb_b1      = (const float*)d_in[6];
    const float* cpb_w2      = (const float*)d_in[7];
    const float* coords      = (const float*)d_in[8];
    const int*   rpi         = (const int*)  d_in[9];
    const float* mask        = (const float*)d_in[10];
    const float* proj_w      = (const float*)d_in[11];
    const float* proj_b      = (const float*)d_in[12];
    float* out = (float*)d_out;

    float* qkv_ptr = nullptr; float* b768_ptr = nullptr;
    __nv_bfloat16 *xhi, *xlo, *aohi, *aolo, *wqhi, *wqlo, *wphi, *wplo;
    cudaGetSymbolAddress((void**)&qkv_ptr, g_qkv);
    cudaGetSymbolAddress((void**)&b768_ptr, g_bias768);
    cudaGetSymbolAddress((void**)&xhi, g_xhi);
    cudaGetSymbolAddress((void**)&xlo, g_xlo);
    cudaGetSymbolAddress((void**)&aohi, g_aohi);
    cudaGetSymbolAddress((void**)&aolo, g_aolo);
    cudaGetSymbolAddress((void**)&wqhi, g_wqhi);
    cudaGetSymbolAddress((void**)&wqlo, g_wqlo);
    cudaGetSymbolAddress((void**)&wphi, g_wphi);
    cudaGetSymbolAddress((void**)&wplo, g_wplo);

    cudaFuncSetAttribute(gemm_bf16x3,
                         cudaFuncAttributeMaxDynamicSharedMemorySize, GSMEM);

    fill_bias_kernel<<<1, 768>>>(q_bias, v_bias);
    cpb_table_kernel<<<169, 64>>>(coords, cpb_w1, cpb_b1, cpb_w2);
    cbias_kernel<<<64 * NH, 256>>>(rpi, mask);

    // pre-split inputs/weights to bf16 hi/lo
    split_kernel<<<(MROWS * DIMC / 4 + 255) / 256, 256>>>(x, xhi, xlo, MROWS * DIMC / 4);
    split_kernel<<<(TDIM * DIMC / 4 + 255) / 256, 256>>>(qkv_w, wqhi, wqlo, TDIM * DIMC / 4);
    split_kernel<<<(DIMC * DIMC / 4 + 255) / 256, 256>>>(proj_w, wphi, wplo, DIMC * DIMC / 4);

    // qkv = x @ qkv_w^T + [q_bias, 0, v_bias]
    gemm_bf16x3<<<dim3(TDIM / 128, MROWS / 128), 256, GSMEM>>>(
        xhi, xlo, wqhi, wqlo, b768_ptr, qkv_ptr, TDIM, DIMC);

    attn_kernel<<<BWIN * NH, 256>>>(logit_scale);

    // out = attn_out @ proj_w^T + proj_b
    gemm_bf16x3<<<dim3(DIMC / 128, MROWS / 128), 256, GSMEM>>>(
        aohi, aolo, wphi, wplo, proj_b, out, DIMC, DIMC);
}

// round 6
// speedup vs baseline: 1.2090x; 1.0321x over previous
#include <cuda_runtime.h>
#include <cuda_bf16.h>
#include <math.h>
#include <stdint.h>
#include <stddef.h>

// ---------------- problem constants ----------------
#define BWIN   4096
#define NTOK   49
#define DIMC   256
#define NH     8
#define HD     32
#define TDIM   768
#define MROWS  (BWIN * NTOK)   // 200704

// ---------------- scratch ----------------
__device__ float g_qkv[(size_t)MROWS * TDIM];
__device__ __nv_bfloat16 g_xhi[(size_t)MROWS * DIMC];
__device__ __nv_bfloat16 g_xlo[(size_t)MROWS * DIMC];
__device__ __nv_bfloat16 g_aohi[(size_t)MROWS * DIMC];
__device__ __nv_bfloat16 g_aolo[(size_t)MROWS * DIMC];
__device__ __nv_bfloat16 g_wqhi[TDIM * DIMC];
__device__ __nv_bfloat16 g_wqlo[TDIM * DIMC];
__device__ __nv_bfloat16 g_wphi[DIMC * DIMC];
__device__ __nv_bfloat16 g_wplo[DIMC * DIMC];
__device__ float g_table[169 * NH];
__device__ float g_bias768[TDIM];
__device__ float g_cbias[64 * NH * 49 * 52];

__device__ __forceinline__ uint32_t pk(__nv_bfloat16 a, __nv_bfloat16 b) {
    return (uint32_t)__bfloat16_as_ushort(a) | ((uint32_t)__bfloat16_as_ushort(b) << 16);
}

// ---------------- split fp32 -> bf16 hi/lo ----------------
__global__ void split_kernel(const float* __restrict__ src,
                             __nv_bfloat16* __restrict__ hi,
                             __nv_bfloat16* __restrict__ lo, int n4) {
    int i = blockIdx.x * 256 + threadIdx.x;
    if (i >= n4) return;
    float4 v = ((const float4*)src)[i];
    __nv_bfloat16 hx = __float2bfloat16(v.x), hy = __float2bfloat16(v.y);
    __nv_bfloat16 hz = __float2bfloat16(v.z), hw = __float2bfloat16(v.w);
    uint2 H = make_uint2(pk(hx, hy), pk(hz, hw));
    uint2 L = make_uint2(
        pk(__float2bfloat16(v.x - __bfloat162float(hx)),
           __float2bfloat16(v.y - __bfloat162float(hy))),
        pk(__float2bfloat16(v.z - __bfloat162float(hz)),
           __float2bfloat16(v.w - __bfloat162float(hw))));
    ((uint2*)hi)[i] = H;
    ((uint2*)lo)[i] = L;
}

// ---------------- tiny setup kernels ----------------
__global__ void fill_bias_kernel(const float* __restrict__ q_bias,
                                 const float* __restrict__ v_bias) {
    int t = threadIdx.x;
    if (t < 256)       g_bias768[t] = q_bias[t];
    else if (t < 512)  g_bias768[t] = 0.f;
    else               g_bias768[t] = v_bias[t - 512];
}

__global__ void cpb_table_kernel(const float* __restrict__ coords,
                                 const float* __restrict__ w1,
                                 const float* __restrict__ b1,
                                 const float* __restrict__ w2) {
    __shared__ float hid[512];
    __shared__ float part[64];
    int r = blockIdx.x;
    int tid = threadIdx.x;
    float c0 = coords[r * 2 + 0];
    float c1 = coords[r * 2 + 1];
    for (int j = tid; j < 512; j += 64) {
        float v = c0 * w1[j * 2 + 0] + c1 * w1[j * 2 + 1] + b1[j];
        hid[j] = v > 0.f ? v : 0.f;
    }
    __syncthreads();
    int head = tid & 7;
    int chunk = tid >> 3;
    float p = 0.f;
    const float* wrow = w2 + head * 512 + chunk * 64;
    const float* hrow = hid + chunk * 64;
#pragma unroll 8
    for (int j = 0; j < 64; ++j) p += hrow[j] * wrow[j];
    part[tid] = p;
    __syncthreads();
    if (tid < 8) {
        float s = 0.f;
#pragma unroll
        for (int c = 0; c < 8; ++c) s += part[c * 8 + tid];
        g_table[r * 8 + tid] = s;
    }
}

__global__ void cbias_kernel(const int* __restrict__ rpi,
                             const float* __restrict__ mask) {
    int wm = blockIdx.x >> 3, h = blockIdx.x & 7;
    float* dst = g_cbias + (size_t)blockIdx.x * (49 * 52);
    const float* m = mask + wm * (NTOK * NTOK);
    for (int idx = threadIdx.x; idx < 49 * 52; idx += 256) {
        int i = idx / 52, j = idx % 52;
        float v = 0.f;
        if (j < 49) {
            float t = g_table[rpi[i * NTOK + j] * NH + h];
            v = 16.f / (1.f + expf(-t)) + m[i * NTOK + j];
        }
        dst[idx] = v;
    }
}

// ================= bf16x3 GEMM, cp.async 3-stage, KC=64, frag pipelining =====
// C[M,N] = A[M,K] @ W[N,K]^T + bias[N]; A,W pre-split bf16 hi/lo.
// 128x128 CTA tile, 8 warps (2M x 4N), warp tile 64x32.

#define KC     64
#define ROWB   144                // 128 data bytes + 16 pad (conflict-free LDSM)
#define MATB   (128 * ROWB)       // 18432
#define STAGEB (4 * MATB)         // 73728: Ah | Al | Wh | Wl
#define NSTG   3
#define GSMEM  (NSTG * STAGEB)    // 221184

__device__ __forceinline__ uint32_t s2u(const void* p) {
    uint32_t a;
    asm("{ .reg .u64 t; cvta.to.shared.u64 t, %1; cvt.u32.u64 %0, t; }"
        : "=r"(a) : "l"(p));
    return a;
}

#define CPA16(saddr, gaddr)                                                   \
    asm volatile("cp.async.cg.shared.global [%0], [%1], 16;"                  \
                 :: "r"(saddr), "l"(gaddr))
#define CPA_COMMIT() asm volatile("cp.async.commit_group;" ::: "memory")
#define CPA_WAIT1()  asm volatile("cp.async.wait_group 1;" ::: "memory")

#define LDSM4(r0, r1, r2, r3, a)                                              \
    asm volatile("ldmatrix.sync.aligned.m8n8.x4.shared.b16 {%0,%1,%2,%3}, [%4];" \
                 : "=r"(r0), "=r"(r1), "=r"(r2), "=r"(r3) : "r"(a))

#define MMA16816(c, a, b)                                                     \
    asm volatile(                                                             \
        "mma.sync.aligned.m16n8k16.row.col.f32.bf16.bf16.f32 "                \
        "{%0,%1,%2,%3},{%4,%5,%6,%7},{%8,%9},{%0,%1,%2,%3};"                  \
        : "+f"((c)[0]), "+f"((c)[1]), "+f"((c)[2]), "+f"((c)[3])              \
        : "r"((a)[0]), "r"((a)[1]), "r"((a)[2]), "r"((a)[3]),                 \
          "r"((b)[0]), "r"((b)[1]))

__global__ __launch_bounds__(256)
void gemm_bf16x3(const __nv_bfloat16* __restrict__ Ahi,
                 const __nv_bfloat16* __restrict__ Alo,
                 const __nv_bfloat16* __restrict__ Whi,
                 const __nv_bfloat16* __restrict__ Wlo,
                 const float* __restrict__ bias, float* __restrict__ C,
                 int N, int K) {
    extern __shared__ char sm[];
    uint32_t smb = s2u(sm);

    int tid = threadIdx.x, lane = tid & 31, wid = tid >> 5;
    int warpM = wid & 1;
    int warpN = wid >> 1;
    size_t rowBlk = (size_t)blockIdx.y * 128;
    int colBlk = blockIdx.x * 128;

    float acc[4][4][4];
#pragma unroll
    for (int mt = 0; mt < 4; ++mt)
#pragma unroll
        for (int nt = 0; nt < 4; ++nt)
#pragma unroll
            for (int u = 0; u < 4; ++u) acc[mt][nt][u] = 0.f;

    const __nv_bfloat16* gA[2] = {Ahi, Alo};
    const __nv_bfloat16* gW[2] = {Whi, Wlo};

    const int NCH = K >> 6;     // 4 for K=256

    // ldmatrix lane bases (same formula validated in R4/R5; ROWB=144)
    int g = lane >> 3, l7 = lane & 7;
    uint32_t aOff = (uint32_t)(warpM * 64 + (g & 1) * 8 + l7) * ROWB + (uint32_t)(g >> 1) * 16;
    uint32_t wOff = (uint32_t)(warpN * 32 + (g >> 1) * 8 + l7) * ROWB + (uint32_t)(g & 1) * 16;

    // gmem->smem: 128 rows x 8 x16B per matrix = 1024 slots, 4 per thread
#define ISSUE_CHUNK(ch)                                                       \
    do {                                                                      \
        uint32_t stg_ = smb + (uint32_t)((ch) % 3) * STAGEB;                  \
        int koff_ = (ch) * KC;                                                \
        _Pragma("unroll")                                                     \
        for (int i_ = 0; i_ < 4; ++i_) {                                      \
            int slot_ = tid + i_ * 256;                                       \
            int lr_ = slot_ >> 3, lc_ = slot_ & 7;                            \
            uint32_t so_ = stg_ + (uint32_t)lr_ * ROWB + (uint32_t)lc_ * 16;  \
            size_t ge_ = (rowBlk + lr_) * (size_t)K + koff_ + lc_ * 8;        \
            size_t gw_ = (size_t)(colBlk + lr_) * K + koff_ + lc_ * 8;        \
            CPA16(so_,            gA[0] + ge_);                               \
            CPA16(so_ + MATB,     gA[1] + ge_);                               \
            CPA16(so_ + 2 * MATB, gW[0] + gw_);                               \
            CPA16(so_ + 3 * MATB, gW[1] + gw_);                               \
        }                                                                     \
    } while (0)

    // fragment buffers (double-buffered across k-steps)
    uint32_t ah[2][4][4], al[2][4][4], wh[2][4][2], wl[2][4][2];

#define LOAD_FRAG(buf, stg, kb)                                               \
    do {                                                                      \
        _Pragma("unroll")                                                     \
        for (int mt_ = 0; mt_ < 4; ++mt_) {                                   \
            uint32_t ad_ = (stg) + aOff + (uint32_t)mt_ * (16 * ROWB) + (kb); \
            LDSM4(ah[buf][mt_][0], ah[buf][mt_][1], ah[buf][mt_][2], ah[buf][mt_][3], ad_); \
            LDSM4(al[buf][mt_][0], al[buf][mt_][1], al[buf][mt_][2], al[buf][mt_][3], ad_ + MATB); \
        }                                                                     \
        _Pragma("unroll")                                                     \
        for (int p_ = 0; p_ < 2; ++p_) {                                      \
            uint32_t wd_ = (stg) + 2 * MATB + wOff + (uint32_t)p_ * (16 * ROWB) + (kb); \
            uint32_t t0_, t1_, t2_, t3_;                                      \
            LDSM4(t0_, t1_, t2_, t3_, wd_);                                   \
            wh[buf][2 * p_][0] = t0_; wh[buf][2 * p_][1] = t1_;               \
            wh[buf][2 * p_ + 1][0] = t2_; wh[buf][2 * p_ + 1][1] = t3_;       \
            LDSM4(t0_, t1_, t2_, t3_, wd_ + MATB);                            \
            wl[buf][2 * p_][0] = t0_; wl[buf][2 * p_][1] = t1_;               \
            wl[buf][2 * p_ + 1][0] = t2_; wl[buf][2 * p_ + 1][1] = t3_;       \
        }                                                                     \
    } while (0)

#define MMA_STEP(buf)                                                         \
    do {                                                                      \
        _Pragma("unroll")                                                     \
        for (int mt_ = 0; mt_ < 4; ++mt_)                                     \
            _Pragma("unroll")                                                 \
            for (int nt_ = 0; nt_ < 4; ++nt_) {                               \
                MMA16816(acc[mt_][nt_], ah[buf][mt_], wh[buf][nt_]);          \
                MMA16816(acc[mt_][nt_], ah[buf][mt_], wl[buf][nt_]);          \
                MMA16816(acc[mt_][nt_], al[buf][mt_], wh[buf][nt_]);          \
            }                                                                 \
    } while (0)

    // prologue: chunks 0 and 1 in flight
    ISSUE_CHUNK(0); CPA_COMMIT();
    ISSUE_CHUNK(1); CPA_COMMIT();

    for (int ch = 0; ch < NCH; ++ch) {
        CPA_WAIT1();            // chunk ch complete
        __syncthreads();
        if (ch + 2 < NCH) ISSUE_CHUNK(ch + 2);
        CPA_COMMIT();           // (possibly empty group keeps count consistent)

        uint32_t stg = smb + (uint32_t)(ch % 3) * STAGEB;
        LOAD_FRAG(0, stg, 0u);
#pragma unroll
        for (int ks = 0; ks < 4; ++ks) {
            if (ks < 3) LOAD_FRAG((ks + 1) & 1, stg, (uint32_t)(ks + 1) * 32);
            MMA_STEP(ks & 1);
        }
    }

    // epilogue
#pragma unroll
    for (int nt = 0; nt < 4; ++nt) {
        int col = colBlk + warpN * 32 + nt * 8 + (lane & 3) * 2;
        float2 bv = *(const float2*)(bias + col);
#pragma unroll
        for (int mt = 0; mt < 4; ++mt) {
            size_t row0 = rowBlk + warpM * 64 + mt * 16 + (lane >> 2);
            float2 o0, o1;
            o0.x = acc[mt][nt][0] + bv.x; o0.y = acc[mt][nt][1] + bv.y;
            o1.x = acc[mt][nt][2] + bv.x; o1.y = acc[mt][nt][3] + bv.y;
            *(float2*)(C + row0 * (size_t)N + col)       = o0;
            *(float2*)(C + (row0 + 8) * (size_t)N + col) = o1;
        }
    }
}

// ================= attention: one block per (window, head) =================
__global__ __launch_bounds__(256)
void attn_kernel(const float* __restrict__ logit_scale) {
    __shared__ float sq[52][36];
    __shared__ float sk[52][36];
    __shared__ float sv[52][36];
    __shared__ float sattn[52][53];

    int blk = blockIdx.x;
    int b = blk >> 3;
    int h = blk & 7;
    int tid = threadIdx.x;
    int wid = tid >> 5, lane = tid & 31;

    for (int idx = tid; idx < NTOK * 8; idx += 256) {
        int n = idx >> 3, d4 = (idx & 7) << 2;
        size_t base = ((size_t)b * NTOK + n) * TDIM + h * HD + d4;
        *(float4*)&sq[n][d4] = *(const float4*)(g_qkv + base);
        *(float4*)&sk[n][d4] = *(const float4*)(g_qkv + base + 256);
        *(float4*)&sv[n][d4] = *(const float4*)(g_qkv + base + 512);
    }
    if (tid < 108) {
        int r = 49 + tid / 36, c = tid % 36;
        sq[r][c] = 0.f; sk[r][c] = 0.f; sv[r][c] = 0.f;
    }
    if (tid < 159) {
        sattn[49 + tid / 53][tid % 53] = 0.f;
    }
    __syncthreads();

    float sc = expf(fminf(logit_scale[h], 4.60517019f));

    for (int r = wid; r < NTOK; r += 8) {
        float qv = sq[r][lane];
        float s = qv * qv;
#pragma unroll
        for (int o = 16; o; o >>= 1) s += __shfl_xor_sync(0xffffffffu, s, o);
        sq[r][lane] = qv * rsqrtf(s + 1e-6f) * sc;
        float kv = sk[r][lane];
        float s2 = kv * kv;
#pragma unroll
        for (int o = 16; o; o >>= 1) s2 += __shfl_xor_sync(0xffffffffu, s2, o);
        sk[r][lane] = kv * rsqrtf(s2 + 1e-6f);
    }
    __syncthreads();

    // QK^T: 13x13 tiles of 4x4
    if (tid < 169) {
        int ti = tid / 13, tj = tid % 13;
        int i0 = 4 * ti, j0 = 4 * tj;
        float a4[4][4];
#pragma unroll
        for (int u = 0; u < 4; ++u)
#pragma unroll
            for (int w = 0; w < 4; ++w) a4[u][w] = 0.f;
#pragma unroll
        for (int d = 0; d < HD; d += 4) {
            float4 qv[4], kv[4];
#pragma unroll
            for (int u = 0; u < 4; ++u) qv[u] = *(const float4*)&sq[i0 + u][d];
#pragma unroll
            for (int w = 0; w < 4; ++w) kv[w] = *(const float4*)&sk[j0 + w][d];
#pragma unroll
            for (int u = 0; u < 4; ++u)
#pragma unroll
                for (int w = 0; w < 4; ++w) {
                    a4[u][w] = fmaf(qv[u].x, kv[w].x, a4[u][w]);
                    a4[u][w] = fmaf(qv[u].y, kv[w].y, a4[u][w]);
                    a4[u][w] = fmaf(qv[u].z, kv[w].z, a4[u][w]);
                    a4[u][w] = fmaf(qv[u].w, kv[w].w, a4[u][w]);
                }
        }
        const float* cb = g_cbias + ((size_t)((b & 63) * NH + h)) * (49 * 52);
#pragma unroll
        for (int u = 0; u < 4; ++u) {
            int i = i0 + u;
            if (i < NTOK) {
#pragma unroll
                for (int w = 0; w < 4; ++w) {
                    int j = j0 + w;
                    if (j < NTOK)
                        sattn[i][j] = a4[u][w] + __ldg(cb + i * 52 + j);
                }
            }
        }
    }
    __syncthreads();

    for (int r = wid; r < NTOK; r += 8) {
        float v0 = sattn[r][lane];
        float v1 = (lane + 32 < NTOK) ? sattn[r][lane + 32] : -1e30f;
        float mx = fmaxf(v0, v1);
#pragma unroll
        for (int o = 16; o; o >>= 1) mx = fmaxf(mx, __shfl_xor_sync(0xffffffffu, mx, o));
        float e0 = expf(v0 - mx);
        float e1 = (lane + 32 < NTOK) ? expf(v1 - mx) : 0.f;
        float sm = e0 + e1;
#pragma unroll
        for (int o = 16; o; o >>= 1) sm += __shfl_xor_sync(0xffffffffu, sm, o);
        float inv = 1.f / sm;
        sattn[r][lane] = e0 * inv;
        if (lane + 32 < NTOK) sattn[r][lane + 32] = e1 * inv;
    }
    __syncthreads();

    // out = attn @ v, write bf16 hi/lo directly
    if (tid < 104) {
        int ti = tid >> 3, dt = tid & 7;
        int i0 = 4 * ti, d0 = 4 * dt;
        float a4[4][4];
#pragma unroll
        for (int u = 0; u < 4; ++u)
#pragma unroll
            for (int w = 0; w < 4; ++w) a4[u][w] = 0.f;
        for (int j = 0; j < NTOK; ++j) {
            float4 vv = *(const float4*)&sv[j][d0];
            float a0 = sattn[i0 + 0][j], a1 = sattn[i0 + 1][j];
            float a2 = sattn[i0 + 2][j], a3 = sattn[i0 + 3][j];
            a4[0][0] = fmaf(a0, vv.x, a4[0][0]); a4[0][1] = fmaf(a0, vv.y, a4[0][1]);
            a4[0][2] = fmaf(a0, vv.z, a4[0][2]); a4[0][3] = fmaf(a0, vv.w, a4[0][3]);
            a4[1][0] = fmaf(a1, vv.x, a4[1][0]); a4[1][1] = fmaf(a1, vv.y, a4[1][1]);
            a4[1][2] = fmaf(a1, vv.z, a4[1][2]); a4[1][3] = fmaf(a1, vv.w, a4[1][3]);
            a4[2][0] = fmaf(a2, vv.x, a4[2][0]); a4[2][1] = fmaf(a2, vv.y, a4[2][1]);
            a4[2][2] = fmaf(a2, vv.z, a4[2][2]); a4[2][3] = fmaf(a2, vv.w, a4[2][3]);
            a4[3][0] = fmaf(a3, vv.x, a4[3][0]); a4[3][1] = fmaf(a3, vv.y, a4[3][1]);
            a4[3][2] = fmaf(a3, vv.z, a4[3][2]); a4[3][3] = fmaf(a3, vv.w, a4[3][3]);
        }
#pragma unroll
        for (int u = 0; u < 4; ++u) {
            int i = i0 + u;
            if (i < NTOK) {
                size_t idx = ((size_t)b * NTOK + i) * DIMC + h * HD + d0;
                __nv_bfloat16 h0 = __float2bfloat16(a4[u][0]);
                __nv_bfloat16 h1 = __float2bfloat16(a4[u][1]);
                __nv_bfloat16 h2 = __float2bfloat16(a4[u][2]);
                __nv_bfloat16 h3 = __float2bfloat16(a4[u][3]);
                uint2 H = make_uint2(pk(h0, h1), pk(h2, h3));
                uint2 L = make_uint2(
                    pk(__float2bfloat16(a4[u][0] - __bfloat162float(h0)),
                       __float2bfloat16(a4[u][1] - __bfloat162float(h1))),
                    pk(__float2bfloat16(a4[u][2] - __bfloat162float(h2)),
                       __float2bfloat16(a4[u][3] - __bfloat162float(h3))));
                *(uint2*)(g_aohi + idx) = H;
                *(uint2*)(g_aolo + idx) = L;
            }
        }
    }
}

// ---------------- launch ----------------
extern "C" void kernel_launch(void* const* d_in, const int* in_sizes, int n_in,
                              void* d_out, int out_size) {
    const float* x           = (const float*)d_in[0];
    const float* qkv_w       = (const float*)d_in[1];
    const float* q_bias      = (const float*)d_in[2];
    const float* v_bias      = (const float*)d_in[3];
    const float* logit_scale = (const float*)d_in[4];
    const float* cpb_w1      = (const float*)d_in[5];
    const float* cpb_b1      = (const float*)d_in[6];
    const float* cpb_w2      = (const float*)d_in[7];
    const float* coords      = (const float*)d_in[8];
    const int*   rpi         = (const int*)  d_in[9];
    const float* mask        = (const float*)d_in[10];
    const float* proj_w      = (const float*)d_in[11];
    const float* proj_b      = (const float*)d_in[12];
    float* out = (float*)d_out;

    float* qkv_ptr = nullptr; float* b768_ptr = nullptr;
    __nv_bfloat16 *xhi, *xlo, *aohi, *aolo, *wqhi, *wqlo, *wphi, *wplo;
    cudaGetSymbolAddress((void**)&qkv_ptr, g_qkv);
    cudaGetSymbolAddress((void**)&b768_ptr, g_bias768);
    cudaGetSymbolAddress((void**)&xhi, g_xhi);
    cudaGetSymbolAddress((void**)&xlo, g_xlo);
    cudaGetSymbolAddress((void**)&aohi, g_aohi);
    cudaGetSymbolAddress((void**)&aolo, g_aolo);
    cudaGetSymbolAddress((void**)&wqhi, g_wqhi);
    cudaGetSymbolAddress((void**)&wqlo, g_wqlo);
    cudaGetSymbolAddress((void**)&wphi, g_wphi);
    cudaGetSymbolAddress((void**)&wplo, g_wplo);

    cudaFuncSetAttribute(gemm_bf16x3,
                         cudaFuncAttributeMaxDynamicSharedMemorySize, GSMEM);

    fill_bias_kernel<<<1, 768>>>(q_bias, v_bias);
    cpb_table_kernel<<<169, 64>>>(coords, cpb_w1, cpb_b1, cpb_w2);
    cbias_kernel<<<64 * NH, 256>>>(rpi, mask);

    // pre-split inputs/weights to bf16 hi/lo
    split_kernel<<<(MROWS * DIMC / 4 + 255) / 256, 256>>>(x, xhi, xlo, MROWS * DIMC / 4);
    split_kernel<<<(TDIM * DIMC / 4 + 255) / 256, 256>>>(qkv_w, wqhi, wqlo, TDIM * DIMC / 4);
    split_kernel<<<(DIMC * DIMC / 4 + 255) / 256, 256>>>(proj_w, wphi, wplo, DIMC * DIMC / 4);

    // qkv = x @ qkv_w^T + [q_bias, 0, v_bias]
    gemm_bf16x3<<<dim3(TDIM / 128, MROWS / 128), 256, GSMEM>>>(
        xhi, xlo, wqhi, wqlo, b768_ptr, qkv_ptr, TDIM, DIMC);

    attn_kernel<<<BWIN * NH, 256>>>(logit_scale);

    // out = attn_out @ proj_w^T + proj_b
    gemm_bf16x3<<<dim3(DIMC / 128, MROWS / 128), 256, GSMEM>>>(
        aohi, aolo, wphi, wplo, proj_b, out, DIMC, DIMC);
}